// round 4
// baseline (speedup 1.0000x reference)
#include <cuda_runtime.h>
#include <cuda_bf16.h>
#include <cstdint>

#define N_NODES 50000
#define N_EDGES 1600000
#define DIM     128
#define N_LAYERS 4
#define N_GRAPHS 512
#define M_TILES  391            // ceil(50000/128)
#define SCAN_BLOCKS 49          // 49*1024 >= 50000

typedef unsigned long long ull;

// ---------------- scratch (static device globals; no allocation) -------------
__device__ int   g_deg[N_NODES];
__device__ int   g_rowstart[N_NODES + 1];
__device__ int   g_cursor[N_NODES];
__device__ int   g_bsum[SCAN_BLOCKS];
__device__ int   g_boff[SCAN_BLOCKS];
__device__ int   g_csr[N_EDGES];
__device__ float g_xbuf[N_NODES * DIM];   // layer output ping buffer
__device__ float g_ybuf[N_NODES * DIM];   // layer output pong buffer

// ---------------- packed fp32x2 FMA (Blackwell FFMA2) ------------------------
__device__ __forceinline__ ull ffma2(ull a, ull b, ull c) {
    ull d;
    asm("fma.rn.f32x2 %0, %1, %2, %3;" : "=l"(d) : "l"(a), "l"(b), "l"(c));
    return d;
}
__device__ __forceinline__ ull dup2(float f) {
    ull d;
    asm("mov.b64 %0, {%1, %1};" : "=l"(d) : "f"(f));
    return d;
}
__device__ __forceinline__ ull pack2(float lo, float hi) {
    ull d;
    asm("mov.b64 %0, {%1, %2};" : "=l"(d) : "f"(lo), "f"(hi));
    return d;
}

// ---------------- CSR build --------------------------------------------------
__global__ void k_hist(const int* __restrict__ ei) {
    int t = blockIdx.x * blockDim.x + threadIdx.x;
    if (t < N_EDGES / 4) {
        int4 d = ((const int4*)(ei + N_EDGES))[t];
        atomicAdd(&g_deg[d.x], 1);
        atomicAdd(&g_deg[d.y], 1);
        atomicAdd(&g_deg[d.z], 1);
        atomicAdd(&g_deg[d.w], 1);
    }
}

__global__ void k_scan_part() {
    __shared__ int sh[1024];
    int t = threadIdx.x;
    int i = blockIdx.x * 1024 + t;
    int v = (i < N_NODES) ? g_deg[i] : 0;
    sh[t] = v;
    __syncthreads();
    #pragma unroll
    for (int off = 1; off < 1024; off <<= 1) {
        int u = (t >= off) ? sh[t - off] : 0;
        __syncthreads();
        sh[t] += u;
        __syncthreads();
    }
    if (i < N_NODES) g_rowstart[i] = sh[t] - v;   // local exclusive
    if (t == 1023) g_bsum[blockIdx.x] = sh[1023];
}

__global__ void k_scan_top() {
    __shared__ int sh[64];
    int t = threadIdx.x;
    int v = (t < SCAN_BLOCKS) ? g_bsum[t] : 0;
    sh[t] = v;
    __syncthreads();
    #pragma unroll
    for (int off = 1; off < 64; off <<= 1) {
        int u = (t >= off) ? sh[t - off] : 0;
        __syncthreads();
        sh[t] += u;
        __syncthreads();
    }
    if (t < SCAN_BLOCKS) g_boff[t] = sh[t] - v;   // exclusive
    if (t == SCAN_BLOCKS - 1) g_rowstart[N_NODES] = sh[t];
}

__global__ void k_scan_add() {
    int t = threadIdx.x;
    int i = blockIdx.x * 1024 + t;
    if (i < N_NODES) {
        int r = g_rowstart[i] + g_boff[blockIdx.x];
        g_rowstart[i] = r;
        g_cursor[i]   = r;
    }
}

__global__ void k_scatter(const int* __restrict__ ei) {
    int t = blockIdx.x * blockDim.x + threadIdx.x;
    if (t < N_EDGES / 4) {
        int4 s = ((const int4*)ei)[t];
        int4 d = ((const int4*)(ei + N_EDGES))[t];
        g_csr[atomicAdd(&g_cursor[d.x], 1)] = s.x;
        g_csr[atomicAdd(&g_cursor[d.y], 1)] = s.y;
        g_csr[atomicAdd(&g_cursor[d.z], 1)] = s.z;
        g_csr[atomicAdd(&g_cursor[d.w], 1)] = s.w;
    }
}

// ---------------- fused layer: gather-agg -> GEMM1(+ReLU) -> GEMM2 ----------
// smem layout (dynamic):
//   sAplain [128][130] f32  (agg result, stride 130: conflict-free stores/reads)
//   sH      [128][130] f32  (hmid tile)
//   sA2k    [2][16][132] ull (double-buffered transposed dup-pair A tile)
//   sWt     [2][16][160] f32 (double-buffered padded W tile)
#define AP_STRIDE 130
#define A2_STRIDE 132
#define W_STRIDE  160
#define OFF_H   (128 * AP_STRIDE)                   // floats
#define OFF_A2  (OFF_H + 128 * AP_STRIDE)           // floats (8B aligned: even)
#define A2_ULLS (16 * A2_STRIDE)
#define OFF_W   (OFF_A2 + 2 * A2_ULLS * 2)          // floats
#define LAYER_SMEM ((OFF_W + 2 * 16 * W_STRIDE) * 4)

__device__ __forceinline__ int widx(int c) { return c + ((c >> 3) << 1); }

__global__ __launch_bounds__(256, 1)
void k_layer(const float* __restrict__ xin,
             const float* __restrict__ W1, const float* __restrict__ b1,
             const float* __restrict__ W2, const float* __restrict__ b2,
             float* __restrict__ xout) {
    extern __shared__ __align__(16) float smem[];
    float* sAplain = smem;
    float* sH      = smem + OFF_H;
    ull*   sA2     = (ull*)(smem + OFF_A2);
    float* sWt     = smem + OFF_W;

    const int tid  = threadIdx.x;
    const int row0 = blockIdx.x * 128;
    const int lane = tid & 31;
    const int warp = tid >> 5;
    const int tr = tid >> 4;        // 0..15
    const int tc = tid & 15;        // 0..15
    const int rbase = tr * 8;
    const int cbase = tc * 8;

    // ================= Phase A: aggregation into sAplain =====================
    const float4* x4 = (const float4*)xin;
    for (int nl = warp; nl < 128; nl += 8) {
        int node = row0 + nl;
        if (node >= N_NODES) break;
        float4 acc = x4[(size_t)node * 32 + lane];
        int s = g_rowstart[node];
        int e = g_rowstart[node + 1];
        int j = s;
        for (; j + 8 <= e; j += 8) {
            int idx[8];
            #pragma unroll
            for (int t = 0; t < 8; t++) idx[t] = __ldg(&g_csr[j + t]);
            float4 v[8];
            #pragma unroll
            for (int t = 0; t < 8; t++) v[t] = __ldg(&x4[(size_t)idx[t] * 32 + lane]);
            #pragma unroll
            for (int t = 0; t < 8; t++) {
                acc.x += v[t].x; acc.y += v[t].y; acc.z += v[t].z; acc.w += v[t].w;
            }
        }
        for (; j < e; j++) {
            int src = __ldg(&g_csr[j]);
            float4 v = __ldg(&x4[(size_t)src * 32 + lane]);
            acc.x += v.x; acc.y += v.y; acc.z += v.z; acc.w += v.w;
        }
        ull* dst = (ull*)&sAplain[nl * AP_STRIDE + 4 * lane];
        dst[0] = pack2(acc.x, acc.y);
        dst[1] = pack2(acc.z, acc.w);
    }
    __syncthreads();

    // ================= Phase B: two GEMMs ====================================
    ull acc[8][4];

    // W prefetch registers
    float4 wpf[2];

    #pragma unroll 1
    for (int g = 0; g < 2; g++) {
        const float* S  = (g == 0) ? sAplain : sH;
        const float* Wg = (g == 0) ? W1 : W2;
        const float* bg = (g == 0) ? b1 : b2;

        #pragma unroll
        for (int i = 0; i < 8; i++)
            #pragma unroll
            for (int j = 0; j < 4; j++) acc[i][j] = 0ULL;

        // prefetch W tile k0=0
        {
            int idx0 = tid * 2, idx1 = tid * 2 + 1;
            wpf[0] = *(const float4*)&Wg[(size_t)(idx0 >> 5) * DIM + (idx0 & 31) * 4];
            wpf[1] = *(const float4*)&Wg[(size_t)(idx1 >> 5) * DIM + (idx1 & 31) * 4];
        }

        #pragma unroll 1
        for (int k0i = 0; k0i < 8; k0i++) {
            const int k0 = k0i * 16;
            const int buf = k0i & 1;
            ull*   sA2b = sA2 + buf * A2_ULLS;
            float* sWb  = sWt + buf * 16 * W_STRIDE;

            // stage W tile from prefetch regs
            #pragma unroll
            for (int i = 0; i < 2; i++) {
                int idx = tid * 2 + i;
                int k = idx >> 5;
                int c = (idx & 31) * 4;
                float* dstp = &sWb[k * W_STRIDE + widx(c)];
                dstp[0] = wpf[i].x; dstp[1] = wpf[i].y;
                dstp[2] = wpf[i].z; dstp[3] = wpf[i].w;
            }
            // stage transposed dup-pair A tile from S
            #pragma unroll
            for (int i = 0; i < 8; i++) {
                int e = tid + i * 256;     // 0..2047
                int kk = e >> 7;           // 0..15
                int r  = e & 127;
                sA2b[kk * A2_STRIDE + r] = dup2(S[r * AP_STRIDE + k0 + kk]);
            }
            __syncthreads();

            // prefetch next W tile
            if (k0i < 7) {
                int nk0 = k0 + 16;
                #pragma unroll
                for (int i = 0; i < 2; i++) {
                    int idx = tid * 2 + i;
                    int k = idx >> 5;
                    int c = (idx & 31) * 4;
                    wpf[i] = *(const float4*)&Wg[(size_t)(nk0 + k) * DIM + c];
                }
            }

            #pragma unroll
            for (int kk = 0; kk < 16; kk++) {
                ull b2v[4];
                const float* wrow = &sWb[kk * W_STRIDE + 10 * tc];
                #pragma unroll
                for (int j = 0; j < 4; j++) b2v[j] = *(const ull*)&wrow[2 * j];
                ull a2[8];
                const ull* arow = &sA2b[kk * A2_STRIDE + rbase];
                #pragma unroll
                for (int i = 0; i < 8; i++) a2[i] = arow[i];
                #pragma unroll
                for (int i = 0; i < 8; i++)
                    #pragma unroll
                    for (int j = 0; j < 4; j++)
                        acc[i][j] = ffma2(a2[i], b2v[j], acc[i][j]);
            }
            __syncthreads();   // safe to restage this buffer next+1 round
        }

        // ---- epilogue ----
        float bv[8];
        #pragma unroll
        for (int j = 0; j < 8; j++) bv[j] = bg[cbase + j];

        if (g == 0) {
            // relu(acc + b1) -> sH
            #pragma unroll
            for (int i = 0; i < 8; i++) {
                int r = rbase + i;
                ull* dst = (ull*)&sH[r * AP_STRIDE + cbase];
                #pragma unroll
                for (int j = 0; j < 4; j++) {
                    ull v = acc[i][j];
                    float lo = fmaxf(__uint_as_float((unsigned)v)         + bv[2 * j],     0.f);
                    float hi = fmaxf(__uint_as_float((unsigned)(v >> 32)) + bv[2 * j + 1], 0.f);
                    dst[j] = pack2(lo, hi);
                }
            }
            __syncthreads();   // sH complete before GEMM2 staging reads it
        } else {
            // acc + b2 -> global xout (guarded)
            #pragma unroll
            for (int i = 0; i < 8; i++) {
                int r = row0 + rbase + i;
                if (r < N_NODES) {
                    float o[8];
                    #pragma unroll
                    for (int j = 0; j < 4; j++) {
                        ull v = acc[i][j];
                        o[2 * j]     = __uint_as_float((unsigned)v)         + bv[2 * j];
                        o[2 * j + 1] = __uint_as_float((unsigned)(v >> 32)) + bv[2 * j + 1];
                    }
                    *(float4*)&xout[(size_t)r * DIM + cbase] =
                        make_float4(o[0], o[1], o[2], o[3]);
                    *(float4*)&xout[(size_t)r * DIM + cbase + 4] =
                        make_float4(o[4], o[5], o[6], o[7]);
                }
            }
        }
    }
}

// ---------------- pooling: batch is sorted -> one block per graph ------------
__global__ void k_pool(const float* __restrict__ x,
                       const int* __restrict__ batch,
                       float* __restrict__ out) {
    int g = blockIdx.x;
    int c = threadIdx.x;   // 0..127
    int a = 0, b = N_NODES;
    while (a < b) { int m = (a + b) >> 1; if (batch[m] < g) a = m + 1; else b = m; }
    int lo = a;
    b = N_NODES;
    while (a < b) { int m = (a + b) >> 1; if (batch[m] < g + 1) a = m + 1; else b = m; }
    int hi = a;
    float s0 = 0.f, s1 = 0.f, s2 = 0.f, s3 = 0.f;
    int i = lo;
    for (; i + 4 <= hi; i += 4) {
        s0 += x[(size_t)(i + 0) * DIM + c];
        s1 += x[(size_t)(i + 1) * DIM + c];
        s2 += x[(size_t)(i + 2) * DIM + c];
        s3 += x[(size_t)(i + 3) * DIM + c];
    }
    for (; i < hi; i++) s0 += x[(size_t)i * DIM + c];
    out[(size_t)g * DIM + c] = (s0 + s1) + (s2 + s3);
}

// ---------------- launch -----------------------------------------------------
extern "C" void kernel_launch(void* const* d_in, const int* in_sizes, int n_in,
                              void* d_out, int out_size) {
    const float* x   = (const float*)d_in[0];
    const int* ei    = (const int*)d_in[1];   // int32 (JAX x64 disabled)
    const int* bat   = (const int*)d_in[2];   // int32
    const float* Ws1 = (const float*)d_in[3];
    const float* bs1 = (const float*)d_in[4];
    const float* Ws2 = (const float*)d_in[5];
    const float* bs2 = (const float*)d_in[6];
    float* out       = (float*)d_out;

    void* p;
    cudaGetSymbolAddress(&p, g_xbuf); float* xb = (float*)p;
    cudaGetSymbolAddress(&p, g_ybuf); float* yb = (float*)p;
    cudaGetSymbolAddress(&p, g_deg);
    cudaMemsetAsync(p, 0, N_NODES * sizeof(int));

    cudaFuncSetAttribute(k_layer, cudaFuncAttributeMaxDynamicSharedMemorySize,
                         LAYER_SMEM);

    k_hist<<<(N_EDGES / 4 + 255) / 256, 256>>>(ei);
    k_scan_part<<<SCAN_BLOCKS, 1024>>>();
    k_scan_top<<<1, 64>>>();
    k_scan_add<<<SCAN_BLOCKS, 1024>>>();
    k_scatter<<<(N_EDGES / 4 + 255) / 256, 256>>>(ei);

    const float* src = x;
    float* dst = xb;
    for (int l = 0; l < N_LAYERS; l++) {
        k_layer<<<M_TILES, 256, LAYER_SMEM>>>(src,
                                              Ws1 + (size_t)l * DIM * DIM,
                                              bs1 + (size_t)l * DIM,
                                              Ws2 + (size_t)l * DIM * DIM,
                                              bs2 + (size_t)l * DIM,
                                              dst);
        src = dst;
        dst = (dst == xb) ? yb : xb;
    }
    k_pool<<<N_GRAPHS, DIM>>>(src, bat, out);
}

// round 5
// speedup vs baseline: 1.3519x; 1.3519x over previous
#include <cuda_runtime.h>
#include <cuda_bf16.h>
#include <cstdint>

#define N_NODES 50000
#define N_EDGES 1600000
#define DIM     128
#define N_LAYERS 4
#define N_GRAPHS 512
#define M_TILES  391            // ceil(50000/128)
#define M_PAD    (M_TILES*128)  // 50048
#define SCAN_BLOCKS 49          // 49*1024 >= 50000

typedef unsigned long long ull;

// ---------------- scratch (static device globals; no allocation) -------------
__device__ int   g_deg[N_NODES];
__device__ int   g_rowstart[N_NODES + 1];
__device__ int   g_cursor[N_NODES];
__device__ int   g_bsum[SCAN_BLOCKS];
__device__ int   g_csr[N_EDGES];
__device__ float g_hin[M_PAD * DIM];   // x + agg (rows >= N_NODES never written)
__device__ float g_hmid[M_PAD * DIM];
__device__ float g_xbuf[M_PAD * DIM];

// ---------------- packed fp32x2 FMA (Blackwell FFMA2) ------------------------
__device__ __forceinline__ ull ffma2(ull a, ull b, ull c) {
    ull d;
    asm("fma.rn.f32x2 %0, %1, %2, %3;" : "=l"(d) : "l"(a), "l"(b), "l"(c));
    return d;
}
__device__ __forceinline__ ull dup2(float f) {
    ull d;
    asm("mov.b64 %0, {%1, %1};" : "=l"(d) : "f"(f));
    return d;
}

// ---------------- CSR build --------------------------------------------------
__global__ void k_hist(const int* __restrict__ ei) {
    int t = blockIdx.x * blockDim.x + threadIdx.x;
    if (t < N_EDGES / 4) {
        int4 d = ((const int4*)(ei + N_EDGES))[t];
        atomicAdd(&g_deg[d.x], 1);
        atomicAdd(&g_deg[d.y], 1);
        atomicAdd(&g_deg[d.z], 1);
        atomicAdd(&g_deg[d.w], 1);
    }
}

__global__ void k_scan_part() {
    __shared__ int sh[1024];
    int t = threadIdx.x;
    int i = blockIdx.x * 1024 + t;
    int v = (i < N_NODES) ? g_deg[i] : 0;
    sh[t] = v;
    __syncthreads();
    #pragma unroll
    for (int off = 1; off < 1024; off <<= 1) {
        int u = (t >= off) ? sh[t - off] : 0;
        __syncthreads();
        sh[t] += u;
        __syncthreads();
    }
    if (i < N_NODES) g_rowstart[i] = sh[t] - v;   // local exclusive
    if (t == 1023) g_bsum[blockIdx.x] = sh[1023];
}

// fused: per-block redundant top-scan of 49 sums + add offset
__global__ void k_scan_add() {
    __shared__ int sb[SCAN_BLOCKS];
    __shared__ int s_total;
    int t = threadIdx.x;
    if (t < SCAN_BLOCKS) sb[t] = g_bsum[t];
    __syncthreads();
    if (t == 0) {
        int run = 0;
        #pragma unroll 1
        for (int i = 0; i < SCAN_BLOCKS; i++) { int v = sb[i]; sb[i] = run; run += v; }
        s_total = run;
    }
    __syncthreads();
    int off = sb[blockIdx.x];
    int i = blockIdx.x * 1024 + t;
    if (i < N_NODES) {
        int r = g_rowstart[i] + off;
        g_rowstart[i] = r;
        g_cursor[i]   = r;
    }
    if (blockIdx.x == 0 && t == 0) g_rowstart[N_NODES] = s_total;
}

__global__ void k_scatter(const int* __restrict__ ei) {
    int t = blockIdx.x * blockDim.x + threadIdx.x;
    if (t < N_EDGES / 4) {
        int4 s = ((const int4*)ei)[t];
        int4 d = ((const int4*)(ei + N_EDGES))[t];
        g_csr[atomicAdd(&g_cursor[d.x], 1)] = s.x;
        g_csr[atomicAdd(&g_cursor[d.y], 1)] = s.y;
        g_csr[atomicAdd(&g_cursor[d.z], 1)] = s.z;
        g_csr[atomicAdd(&g_cursor[d.w], 1)] = s.w;
    }
}

// ---------------- aggregation: hout[n] = xin[n] + sum_{s in N(n)} xin[s] -----
__global__ void k_agg(const float* __restrict__ xin, float* __restrict__ hout) {
    int warp = (blockIdx.x * blockDim.x + threadIdx.x) >> 5;
    int lane = threadIdx.x & 31;
    if (warp >= N_NODES) return;
    const float4* x4 = (const float4*)xin;
    float4 acc = x4[(size_t)warp * 32 + lane];
    int s = g_rowstart[warp];
    int e = g_rowstart[warp + 1];
    int j = s;
    for (; j + 8 <= e; j += 8) {
        int idx[8];
        #pragma unroll
        for (int t = 0; t < 8; t++) idx[t] = __ldg(&g_csr[j + t]);
        float4 v[8];
        #pragma unroll
        for (int t = 0; t < 8; t++) v[t] = __ldg(&x4[(size_t)idx[t] * 32 + lane]);
        #pragma unroll
        for (int t = 0; t < 8; t++) {
            acc.x += v[t].x; acc.y += v[t].y; acc.z += v[t].z; acc.w += v[t].w;
        }
    }
    for (; j < e; j++) {
        int src = __ldg(&g_csr[j]);
        float4 v = __ldg(&x4[(size_t)src * 32 + lane]);
        acc.x += v.x; acc.y += v.y; acc.z += v.z; acc.w += v.w;
    }
    ((float4*)hout)[(size_t)warp * 32 + lane] = acc;
}

// ---------------- fp32x2 GEMM, streamed + double-buffered tiles --------------
// smem: sW [2][16][160] f32 (padded, conflict-free col-pair LDS.64)
//       sA2[2][16][132] ull (transposed dup-pair A tile)
#define W_STRIDE  160
#define A2_STRIDE 132
#define WT_FLOATS (16 * W_STRIDE)       // 2560 floats per buffer
#define A2_ULLS   (16 * A2_STRIDE)      // 2112 ulls per buffer
#define OFF_A2f   (2 * WT_FLOATS)       // float offset of sA2 (even -> 8B ok)
#define GEMM_SMEM ((2 * WT_FLOATS) * 4 + (2 * A2_ULLS) * 8)   // 54272 B

__device__ __forceinline__ int widx(int c) { return c + ((c >> 3) << 1); }

template <bool RELU>
__global__ __launch_bounds__(256, 2) void k_gemm(const float* __restrict__ A,
                                                 const float* __restrict__ W,
                                                 const float* __restrict__ bias,
                                                 float* __restrict__ C) {
    extern __shared__ __align__(16) float smem[];
    float* sW  = smem;
    ull*   sA2 = (ull*)(smem + OFF_A2f);

    const int tid  = threadIdx.x;
    const int row0 = blockIdx.x * 128;
    const int tr = tid >> 4;        // 0..15
    const int tc = tid & 15;        // 0..15
    const int rbase = tr * 8;
    const int cbase = tc * 8;

    // per-thread staging coordinates (constant across iters)
    const int wk0 = (tid * 2) >> 5,       wc0 = ((tid * 2) & 31) * 4;
    const int wk1 = (tid * 2 + 1) >> 5,   wc1 = ((tid * 2 + 1) & 31) * 4;
    const int ar0 = (tid * 2) >> 2,       akc0 = ((tid * 2) & 3) * 4;
    const int ar1 = (tid * 2 + 1) >> 2,   akc1 = ((tid * 2 + 1) & 3) * 4;

    ull acc[8][4];
    #pragma unroll
    for (int i = 0; i < 8; i++)
        #pragma unroll
        for (int j = 0; j < 4; j++) acc[i][j] = 0ULL;

    // prefetch k0 = 0
    float4 wpf0 = *(const float4*)&W[(size_t)wk0 * DIM + wc0];
    float4 wpf1 = *(const float4*)&W[(size_t)wk1 * DIM + wc1];
    float4 apf0 = *(const float4*)&A[(size_t)(row0 + ar0) * DIM + akc0];
    float4 apf1 = *(const float4*)&A[(size_t)(row0 + ar1) * DIM + akc1];

    #pragma unroll 1
    for (int k0i = 0; k0i < 8; k0i++) {
        const int buf = k0i & 1;
        float* sWb  = sW  + buf * WT_FLOATS;
        ull*   sA2b = sA2 + buf * A2_ULLS;

        // stage from prefetch regs
        {
            float* d0 = &sWb[wk0 * W_STRIDE + widx(wc0)];
            d0[0] = wpf0.x; d0[1] = wpf0.y; d0[2] = wpf0.z; d0[3] = wpf0.w;
            float* d1 = &sWb[wk1 * W_STRIDE + widx(wc1)];
            d1[0] = wpf1.x; d1[1] = wpf1.y; d1[2] = wpf1.z; d1[3] = wpf1.w;
            sA2b[(akc0 + 0) * A2_STRIDE + ar0] = dup2(apf0.x);
            sA2b[(akc0 + 1) * A2_STRIDE + ar0] = dup2(apf0.y);
            sA2b[(akc0 + 2) * A2_STRIDE + ar0] = dup2(apf0.z);
            sA2b[(akc0 + 3) * A2_STRIDE + ar0] = dup2(apf0.w);
            sA2b[(akc1 + 0) * A2_STRIDE + ar1] = dup2(apf1.x);
            sA2b[(akc1 + 1) * A2_STRIDE + ar1] = dup2(apf1.y);
            sA2b[(akc1 + 2) * A2_STRIDE + ar1] = dup2(apf1.z);
            sA2b[(akc1 + 3) * A2_STRIDE + ar1] = dup2(apf1.w);
        }
        __syncthreads();

        // prefetch next k-slice (overlaps compute below)
        if (k0i < 7) {
            const int nk0 = (k0i + 1) * 16;
            wpf0 = *(const float4*)&W[(size_t)(nk0 + wk0) * DIM + wc0];
            wpf1 = *(const float4*)&W[(size_t)(nk0 + wk1) * DIM + wc1];
            apf0 = *(const float4*)&A[(size_t)(row0 + ar0) * DIM + nk0 + akc0];
            apf1 = *(const float4*)&A[(size_t)(row0 + ar1) * DIM + nk0 + akc1];
        }

        #pragma unroll
        for (int kk = 0; kk < 16; kk++) {
            ull b2v[4];
            const float* wrow = &sWb[kk * W_STRIDE + 10 * tc];
            #pragma unroll
            for (int j = 0; j < 4; j++) b2v[j] = *(const ull*)&wrow[2 * j];
            ull a2[8];
            const ull* arow = &sA2b[kk * A2_STRIDE + rbase];
            #pragma unroll
            for (int i = 0; i < 8; i++) a2[i] = arow[i];
            #pragma unroll
            for (int i = 0; i < 8; i++)
                #pragma unroll
                for (int j = 0; j < 4; j++)
                    acc[i][j] = ffma2(a2[i], b2v[j], acc[i][j]);
        }
        // single sync per iter: next iter writes buf^1; buf rewritten only
        // after the NEXT sync, by which time all threads finished this compute
    }

    float bv[8];
    #pragma unroll
    for (int j = 0; j < 8; j++) bv[j] = bias[cbase + j];

    #pragma unroll
    for (int i = 0; i < 8; i++) {
        int r = row0 + rbase + i;
        float o[8];
        #pragma unroll
        for (int j = 0; j < 4; j++) {
            ull v = acc[i][j];
            float lo = __uint_as_float((unsigned)v)         + bv[2 * j];
            float hi = __uint_as_float((unsigned)(v >> 32)) + bv[2 * j + 1];
            if (RELU) { lo = fmaxf(lo, 0.f); hi = fmaxf(hi, 0.f); }
            o[2 * j] = lo; o[2 * j + 1] = hi;
        }
        *(float4*)&C[(size_t)r * DIM + cbase]     = make_float4(o[0], o[1], o[2], o[3]);
        *(float4*)&C[(size_t)r * DIM + cbase + 4] = make_float4(o[4], o[5], o[6], o[7]);
    }
}

// ---------------- pooling: batch is sorted -> one block per graph ------------
__global__ void k_pool(const float* __restrict__ x,
                       const int* __restrict__ batch,
                       float* __restrict__ out) {
    int g = blockIdx.x;
    int c = threadIdx.x;   // 0..127
    int a = 0, b = N_NODES;
    while (a < b) { int m = (a + b) >> 1; if (batch[m] < g) a = m + 1; else b = m; }
    int lo = a;
    b = N_NODES;
    while (a < b) { int m = (a + b) >> 1; if (batch[m] < g + 1) a = m + 1; else b = m; }
    int hi = a;
    float s0 = 0.f, s1 = 0.f, s2 = 0.f, s3 = 0.f;
    int i = lo;
    for (; i + 4 <= hi; i += 4) {
        s0 += x[(size_t)(i + 0) * DIM + c];
        s1 += x[(size_t)(i + 1) * DIM + c];
        s2 += x[(size_t)(i + 2) * DIM + c];
        s3 += x[(size_t)(i + 3) * DIM + c];
    }
    for (; i < hi; i++) s0 += x[(size_t)i * DIM + c];
    out[(size_t)g * DIM + c] = (s0 + s1) + (s2 + s3);
}

// ---------------- launch -----------------------------------------------------
extern "C" void kernel_launch(void* const* d_in, const int* in_sizes, int n_in,
                              void* d_out, int out_size) {
    const float* x   = (const float*)d_in[0];
    const int* ei    = (const int*)d_in[1];   // int32 (JAX x64 disabled)
    const int* bat   = (const int*)d_in[2];   // int32
    const float* Ws1 = (const float*)d_in[3];
    const float* bs1 = (const float*)d_in[4];
    const float* Ws2 = (const float*)d_in[5];
    const float* bs2 = (const float*)d_in[6];
    float* out       = (float*)d_out;

    void* p;
    cudaGetSymbolAddress(&p, g_hin);  float* hin  = (float*)p;
    cudaGetSymbolAddress(&p, g_hmid); float* hmid = (float*)p;
    cudaGetSymbolAddress(&p, g_xbuf); float* xb   = (float*)p;
    cudaGetSymbolAddress(&p, g_deg);
    cudaMemsetAsync(p, 0, N_NODES * sizeof(int));

    cudaFuncSetAttribute(k_gemm<true>,  cudaFuncAttributeMaxDynamicSharedMemorySize, GEMM_SMEM);
    cudaFuncSetAttribute(k_gemm<false>, cudaFuncAttributeMaxDynamicSharedMemorySize, GEMM_SMEM);

    k_hist<<<(N_EDGES / 4 + 255) / 256, 256>>>(ei);
    k_scan_part<<<SCAN_BLOCKS, 1024>>>();
    k_scan_add<<<SCAN_BLOCKS, 1024>>>();
    k_scatter<<<(N_EDGES / 4 + 255) / 256, 256>>>(ei);

    const int agg_blocks = (N_NODES * 32 + 255) / 256;
    for (int l = 0; l < N_LAYERS; l++) {
        const float* xin = (l == 0) ? x : xb;
        k_agg<<<agg_blocks, 256>>>(xin, hin);
        k_gemm<true><<<M_TILES, 256, GEMM_SMEM>>>(hin, Ws1 + (size_t)l * DIM * DIM,
                                                  bs1 + (size_t)l * DIM, hmid);
        k_gemm<false><<<M_TILES, 256, GEMM_SMEM>>>(hmid, Ws2 + (size_t)l * DIM * DIM,
                                                   bs2 + (size_t)l * DIM, xb);
    }
    k_pool<<<N_GRAPHS, DIM>>>(xb, bat, out);
}

// round 10
// speedup vs baseline: 1.4368x; 1.0628x over previous
#include <cuda_runtime.h>
#include <cuda_bf16.h>
#include <cstdint>

#define N_NODES 50000
#define N_EDGES 1600000
#define DIM     128
#define N_LAYERS 4
#define N_GRAPHS 512
#define M_TILES  391            // ceil(50000/128)
#define M_PAD    (M_TILES*128)  // 50048
#define SCAN_BLOCKS 49          // 49*1024 >= 50000

typedef unsigned long long ull;

// ---------------- scratch (static device globals; no allocation) -------------
__device__ int   g_deg[N_NODES];
__device__ int   g_rowstart[N_NODES + 1];
__device__ int   g_cursor[N_NODES];
__device__ int   g_bsum[SCAN_BLOCKS];
__device__ int   g_csr[N_EDGES];
__device__ float g_hin[M_PAD * DIM];   // x + agg (rows >= N_NODES stay 0 forever)
__device__ float g_xbuf[M_PAD * DIM];  // layer output

// ---------------- packed fp32x2 FMA (Blackwell FFMA2) ------------------------
__device__ __forceinline__ ull ffma2(ull a, ull b, ull c) {
    ull d;
    asm("fma.rn.f32x2 %0, %1, %2, %3;" : "=l"(d) : "l"(a), "l"(b), "l"(c));
    return d;
}
__device__ __forceinline__ ull dup2(float f) {
    ull d;
    asm("mov.b64 %0, {%1, %1};" : "=l"(d) : "f"(f));
    return d;
}
__device__ __forceinline__ ull pack2(float lo, float hi) {
    ull d;
    asm("mov.b64 %0, {%1, %2};" : "=l"(d) : "f"(lo), "f"(hi));
    return d;
}

// ---------------- CSR build --------------------------------------------------
__global__ void k_hist(const int* __restrict__ ei) {
    int t = blockIdx.x * blockDim.x + threadIdx.x;
    if (t < N_EDGES / 4) {
        int4 d = ((const int4*)(ei + N_EDGES))[t];
        atomicAdd(&g_deg[d.x], 1);
        atomicAdd(&g_deg[d.y], 1);
        atomicAdd(&g_deg[d.z], 1);
        atomicAdd(&g_deg[d.w], 1);
    }
}

__global__ void k_scan_part() {
    __shared__ int sh[1024];
    int t = threadIdx.x;
    int i = blockIdx.x * 1024 + t;
    int v = (i < N_NODES) ? g_deg[i] : 0;
    sh[t] = v;
    __syncthreads();
    #pragma unroll
    for (int off = 1; off < 1024; off <<= 1) {
        int u = (t >= off) ? sh[t - off] : 0;
        __syncthreads();
        sh[t] += u;
        __syncthreads();
    }
    if (i < N_NODES) g_rowstart[i] = sh[t] - v;   // local exclusive
    if (t == 1023) g_bsum[blockIdx.x] = sh[1023];
}

// fused: per-block redundant top-scan of 49 sums + add offset
__global__ void k_scan_add() {
    __shared__ int sb[SCAN_BLOCKS];
    __shared__ int s_total;
    int t = threadIdx.x;
    if (t < SCAN_BLOCKS) sb[t] = g_bsum[t];
    __syncthreads();
    if (t == 0) {
        int run = 0;
        #pragma unroll 1
        for (int i = 0; i < SCAN_BLOCKS; i++) { int v = sb[i]; sb[i] = run; run += v; }
        s_total = run;
    }
    __syncthreads();
    int off = sb[blockIdx.x];
    int i = blockIdx.x * 1024 + t;
    if (i < N_NODES) {
        int r = g_rowstart[i] + off;
        g_rowstart[i] = r;
        g_cursor[i]   = r;
    }
    if (blockIdx.x == 0 && t == 0) g_rowstart[N_NODES] = s_total;
}

__global__ void k_scatter(const int* __restrict__ ei) {
    int t = blockIdx.x * blockDim.x + threadIdx.x;
    if (t < N_EDGES / 4) {
        int4 s = ((const int4*)ei)[t];
        int4 d = ((const int4*)(ei + N_EDGES))[t];
        g_csr[atomicAdd(&g_cursor[d.x], 1)] = s.x;
        g_csr[atomicAdd(&g_cursor[d.y], 1)] = s.y;
        g_csr[atomicAdd(&g_cursor[d.z], 1)] = s.z;
        g_csr[atomicAdd(&g_cursor[d.w], 1)] = s.w;
    }
}

// ---------------- aggregation: hout[n] = xin[n] + sum_{s in N(n)} xin[s] -----
__global__ void k_agg(const float* __restrict__ xin, float* __restrict__ hout) {
    int warp = (blockIdx.x * blockDim.x + threadIdx.x) >> 5;
    int lane = threadIdx.x & 31;
    if (warp >= N_NODES) return;
    const float4* x4 = (const float4*)xin;
    float4 acc = x4[(size_t)warp * 32 + lane];
    int s = g_rowstart[warp];
    int e = g_rowstart[warp + 1];
    int j = s;
    for (; j + 8 <= e; j += 8) {
        int idx[8];
        #pragma unroll
        for (int t = 0; t < 8; t++) idx[t] = __ldg(&g_csr[j + t]);
        float4 v[8];
        #pragma unroll
        for (int t = 0; t < 8; t++) v[t] = __ldg(&x4[(size_t)idx[t] * 32 + lane]);
        #pragma unroll
        for (int t = 0; t < 8; t++) {
            acc.x += v[t].x; acc.y += v[t].y; acc.z += v[t].z; acc.w += v[t].w;
        }
    }
    for (; j < e; j++) {
        int src = __ldg(&g_csr[j]);
        float4 v = __ldg(&x4[(size_t)src * 32 + lane]);
        acc.x += v.x; acc.y += v.y; acc.z += v.z; acc.w += v.w;
    }
    ((float4*)hout)[(size_t)warp * 32 + lane] = acc;
}

// ---------------- fused MLP: C = relu(A@W1+b1)@W2 + b2 ----------------------
// smem: sW  [16][160] f32  (padded, conflict-free col-pair LDS.64)
//       sA2 [16][132] ull  (transposed dup-pair A tile)
//       sH  [128][130] f32 (hmid tile, row-major)
#define W_STRIDE  160
#define A2_STRIDE 132
#define H_STRIDE  130
#define WT_FLOATS (16 * W_STRIDE)        // 2560
#define A2_ULLS   (16 * A2_STRIDE)       // 2112
#define OFF_A2f   WT_FLOATS              // float offset (10240 B, 16B mult)
#define OFF_Hf    (WT_FLOATS + A2_ULLS * 2)   // 2560+4224=6784 floats
#define MLP_SMEM  ((OFF_Hf + 128 * H_STRIDE) * 4)   // 93,696 B

__device__ __forceinline__ int widx(int c) { return c + ((c >> 3) << 1); }

__global__ __launch_bounds__(256, 2) void k_mlp(const float* __restrict__ A,
                                                const float* __restrict__ W1,
                                                const float* __restrict__ b1,
                                                const float* __restrict__ W2,
                                                const float* __restrict__ b2,
                                                float* __restrict__ C) {
    extern __shared__ __align__(16) float smem[];
    float* sW  = smem;
    ull*   sA2 = (ull*)(smem + OFF_A2f);
    float* sH  = smem + OFF_Hf;

    const int tid  = threadIdx.x;
    const int row0 = blockIdx.x * 128;
    const int tr = tid >> 4;        // 0..15
    const int tc = tid & 15;        // 0..15
    const int rbase = tr * 8;
    const int cbase = tc * 8;

    // per-thread staging coordinates (constant across iters)
    const int wk0 = (tid * 2) >> 5,       wc0 = ((tid * 2) & 31) * 4;
    const int wk1 = (tid * 2 + 1) >> 5,   wc1 = ((tid * 2 + 1) & 31) * 4;
    const int ar0 = (tid * 2) >> 2,       akc0 = ((tid * 2) & 3) * 4;
    const int ar1 = (tid * 2 + 1) >> 2,   akc1 = ((tid * 2 + 1) & 3) * 4;

    ull acc[8][4];

    // ===================== GEMM1: sH = relu(A@W1 + b1) =======================
    #pragma unroll
    for (int i = 0; i < 8; i++)
        #pragma unroll
        for (int j = 0; j < 4; j++) acc[i][j] = 0ULL;

    float4 wpf0 = *(const float4*)&W1[(size_t)wk0 * DIM + wc0];
    float4 wpf1 = *(const float4*)&W1[(size_t)wk1 * DIM + wc1];
    float4 apf0 = *(const float4*)&A[(size_t)(row0 + ar0) * DIM + akc0];
    float4 apf1 = *(const float4*)&A[(size_t)(row0 + ar1) * DIM + akc1];

    #pragma unroll 1
    for (int k0i = 0; k0i < 8; k0i++) {
        if (k0i > 0) __syncthreads();   // prior compute done before restage
        {
            float* d0 = &sW[wk0 * W_STRIDE + widx(wc0)];
            d0[0] = wpf0.x; d0[1] = wpf0.y; d0[2] = wpf0.z; d0[3] = wpf0.w;
            float* d1 = &sW[wk1 * W_STRIDE + widx(wc1)];
            d1[0] = wpf1.x; d1[1] = wpf1.y; d1[2] = wpf1.z; d1[3] = wpf1.w;
            sA2[(akc0 + 0) * A2_STRIDE + ar0] = dup2(apf0.x);
            sA2[(akc0 + 1) * A2_STRIDE + ar0] = dup2(apf0.y);
            sA2[(akc0 + 2) * A2_STRIDE + ar0] = dup2(apf0.z);
            sA2[(akc0 + 3) * A2_STRIDE + ar0] = dup2(apf0.w);
            sA2[(akc1 + 0) * A2_STRIDE + ar1] = dup2(apf1.x);
            sA2[(akc1 + 1) * A2_STRIDE + ar1] = dup2(apf1.y);
            sA2[(akc1 + 2) * A2_STRIDE + ar1] = dup2(apf1.z);
            sA2[(akc1 + 3) * A2_STRIDE + ar1] = dup2(apf1.w);
        }
        __syncthreads();
        if (k0i < 7) {
            const int nk0 = (k0i + 1) * 16;
            wpf0 = *(const float4*)&W1[(size_t)(nk0 + wk0) * DIM + wc0];
            wpf1 = *(const float4*)&W1[(size_t)(nk0 + wk1) * DIM + wc1];
            apf0 = *(const float4*)&A[(size_t)(row0 + ar0) * DIM + nk0 + akc0];
            apf1 = *(const float4*)&A[(size_t)(row0 + ar1) * DIM + nk0 + akc1];
        }
        #pragma unroll
        for (int kk = 0; kk < 16; kk++) {
            ull b2v[4];
            const float* wrow = &sW[kk * W_STRIDE + 10 * tc];
            #pragma unroll
            for (int j = 0; j < 4; j++) b2v[j] = *(const ull*)&wrow[2 * j];
            ull a2[8];
            const ull* arow = &sA2[kk * A2_STRIDE + rbase];
            #pragma unroll
            for (int i = 0; i < 8; i++) a2[i] = arow[i];
            #pragma unroll
            for (int i = 0; i < 8; i++)
                #pragma unroll
                for (int j = 0; j < 4; j++)
                    acc[i][j] = ffma2(a2[i], b2v[j], acc[i][j]);
        }
    }

    // epilogue 1: relu(acc + b1) -> sH (row-major; distinct region, no sync yet)
    {
        float bv[8];
        #pragma unroll
        for (int j = 0; j < 8; j++) bv[j] = b1[cbase + j];
        #pragma unroll
        for (int i = 0; i < 8; i++) {
            ull* dst = (ull*)&sH[(rbase + i) * H_STRIDE + cbase];
            #pragma unroll
            for (int j = 0; j < 4; j++) {
                ull v = acc[i][j];
                float lo = fmaxf(__uint_as_float((unsigned)v)         + bv[2 * j],     0.f);
                float hi = fmaxf(__uint_as_float((unsigned)(v >> 32)) + bv[2 * j + 1], 0.f);
                dst[j] = pack2(lo, hi);
            }
        }
    }
    // prefetch W2 k0=0 while others finish epilogue
    wpf0 = *(const float4*)&W2[(size_t)wk0 * DIM + wc0];
    wpf1 = *(const float4*)&W2[(size_t)wk1 * DIM + wc1];
    __syncthreads();   // sH complete; also prior sW/sA2 reads done

    // ===================== GEMM2: C = sH@W2 + b2 =============================
    #pragma unroll
    for (int i = 0; i < 8; i++)
        #pragma unroll
        for (int j = 0; j < 4; j++) acc[i][j] = 0ULL;

    #pragma unroll 1
    for (int k0i = 0; k0i < 8; k0i++) {
        const int k0 = k0i * 16;
        if (k0i > 0) __syncthreads();
        {
            float* d0 = &sW[wk0 * W_STRIDE + widx(wc0)];
            d0[0] = wpf0.x; d0[1] = wpf0.y; d0[2] = wpf0.z; d0[3] = wpf0.w;
            float* d1 = &sW[wk1 * W_STRIDE + widx(wc1)];
            d1[0] = wpf1.x; d1[1] = wpf1.y; d1[2] = wpf1.z; d1[3] = wpf1.w;
            // stage transposed dup-pair A tile from sH (smem -> smem)
            #pragma unroll
            for (int i = 0; i < 8; i++) {
                int e  = tid + i * 256;    // 0..2047
                int kk = e >> 7;           // 0..15
                int r  = e & 127;
                sA2[kk * A2_STRIDE + r] = dup2(sH[r * H_STRIDE + k0 + kk]);
            }
        }
        __syncthreads();
        if (k0i < 7) {
            const int nk0 = k0 + 16;
            wpf0 = *(const float4*)&W2[(size_t)(nk0 + wk0) * DIM + wc0];
            wpf1 = *(const float4*)&W2[(size_t)(nk0 + wk1) * DIM + wc1];
        }
        #pragma unroll
        for (int kk = 0; kk < 16; kk++) {
            ull b2v[4];
            const float* wrow = &sW[kk * W_STRIDE + 10 * tc];
            #pragma unroll
            for (int j = 0; j < 4; j++) b2v[j] = *(const ull*)&wrow[2 * j];
            ull a2[8];
            const ull* arow = &sA2[kk * A2_STRIDE + rbase];
            #pragma unroll
            for (int i = 0; i < 8; i++) a2[i] = arow[i];
            #pragma unroll
            for (int i = 0; i < 8; i++)
                #pragma unroll
                for (int j = 0; j < 4; j++)
                    acc[i][j] = ffma2(a2[i], b2v[j], acc[i][j]);
        }
    }

    // epilogue 2: acc + b2 -> global (guarded)
    {
        float bv[8];
        #pragma unroll
        for (int j = 0; j < 8; j++) bv[j] = b2[cbase + j];
        #pragma unroll
        for (int i = 0; i < 8; i++) {
            int r = row0 + rbase + i;
            if (r < N_NODES) {
                float o[8];
                #pragma unroll
                for (int j = 0; j < 4; j++) {
                    ull v = acc[i][j];
                    o[2 * j]     = __uint_as_float((unsigned)v)         + bv[2 * j];
                    o[2 * j + 1] = __uint_as_float((unsigned)(v >> 32)) + bv[2 * j + 1];
                }
                *(float4*)&C[(size_t)r * DIM + cbase]     = make_float4(o[0], o[1], o[2], o[3]);
                *(float4*)&C[(size_t)r * DIM + cbase + 4] = make_float4(o[4], o[5], o[6], o[7]);
            }
        }
    }
}

// ---------------- pooling: batch is sorted -> one block per graph ------------
__global__ void k_pool(const float* __restrict__ x,
                       const int* __restrict__ batch,
                       float* __restrict__ out) {
    int g = blockIdx.x;
    int c = threadIdx.x;   // 0..127
    int a = 0, b = N_NODES;
    while (a < b) { int m = (a + b) >> 1; if (batch[m] < g) a = m + 1; else b = m; }
    int lo = a;
    b = N_NODES;
    while (a < b) { int m = (a + b) >> 1; if (batch[m] < g + 1) a = m + 1; else b = m; }
    int hi = a;
    float s0 = 0.f, s1 = 0.f, s2 = 0.f, s3 = 0.f;
    int i = lo;
    for (; i + 4 <= hi; i += 4) {
        s0 += x[(size_t)(i + 0) * DIM + c];
        s1 += x[(size_t)(i + 1) * DIM + c];
        s2 += x[(size_t)(i + 2) * DIM + c];
        s3 += x[(size_t)(i + 3) * DIM + c];
    }
    for (; i < hi; i++) s0 += x[(size_t)i * DIM + c];
    out[(size_t)g * DIM + c] = (s0 + s1) + (s2 + s3);
}

// ---------------- launch -----------------------------------------------------
extern "C" void kernel_launch(void* const* d_in, const int* in_sizes, int n_in,
                              void* d_out, int out_size) {
    const float* x   = (const float*)d_in[0];
    const int* ei    = (const int*)d_in[1];   // int32 (JAX x64 disabled)
    const int* bat   = (const int*)d_in[2];   // int32
    const float* Ws1 = (const float*)d_in[3];
    const float* bs1 = (const float*)d_in[4];
    const float* Ws2 = (const float*)d_in[5];
    const float* bs2 = (const float*)d_in[6];
    float* out       = (float*)d_out;

    void* p;
    cudaGetSymbolAddress(&p, g_hin);  float* hin = (float*)p;
    cudaGetSymbolAddress(&p, g_xbuf); float* xb  = (float*)p;
    cudaGetSymbolAddress(&p, g_deg);
    cudaMemsetAsync(p, 0, N_NODES * sizeof(int));

    cudaFuncSetAttribute(k_mlp, cudaFuncAttributeMaxDynamicSharedMemorySize, MLP_SMEM);

    k_hist<<<(N_EDGES / 4 + 255) / 256, 256>>>(ei);
    k_scan_part<<<SCAN_BLOCKS, 1024>>>();
    k_scan_add<<<SCAN_BLOCKS, 1024>>>();
    k_scatter<<<(N_EDGES / 4 + 255) / 256, 256>>>(ei);

    const int agg_blocks = (N_NODES * 32 + 255) / 256;
    for (int l = 0; l < N_LAYERS; l++) {
        const float* xin = (l == 0) ? x : xb;
        k_agg<<<agg_blocks, 256>>>(xin, hin);
        k_mlp<<<M_TILES, 256, MLP_SMEM>>>(hin,
                                          Ws1 + (size_t)l * DIM * DIM,
                                          bs1 + (size_t)l * DIM,
                                          Ws2 + (size_t)l * DIM * DIM,
                                          bs2 + (size_t)l * DIM,
                                          xb);
    }
    k_pool<<<N_GRAPHS, DIM>>>(xb, bat, out);
}